// round 1
// baseline (speedup 1.0000x reference)
#include <cuda_runtime.h>
#include <cuda_bf16.h>
#include <cstdint>

#define KDIM 4096
#define NDIM 11008
#define MMAX 8192

// ---------------- scratch (static device globals — no runtime allocation) ---
__device__ float d_scale_col[NDIM];
__device__ float d_x_scale[MMAX];
__device__ __nv_bfloat16 d_qw[(size_t)NDIM * KDIM];
__device__ __nv_bfloat16 d_qx[(size_t)MMAX * KDIM];
__device__ int d_mask[KDIM];
__device__ int d_oidx[KDIM];
__device__ int d_ocnt;

// ---------------- small helpers -------------------------------------------
__device__ __forceinline__ void cp_async16(uint32_t smem, const void* gmem) {
    asm volatile("cp.async.cg.shared.global [%0], [%1], 16;\n" :: "r"(smem), "l"(gmem));
}
__device__ __forceinline__ void cp_commit() { asm volatile("cp.async.commit_group;\n"); }
template <int N> __device__ __forceinline__ void cp_wait() {
    asm volatile("cp.async.wait_group %0;\n" :: "n"(N));
}
__device__ __forceinline__ void ldm_x4(uint32_t* r, const void* p) {
    uint32_t a = (uint32_t)__cvta_generic_to_shared(p);
    asm volatile("ldmatrix.sync.aligned.m8n8.x4.shared.b16 {%0,%1,%2,%3}, [%4];"
                 : "=r"(r[0]), "=r"(r[1]), "=r"(r[2]), "=r"(r[3]) : "r"(a));
}
__device__ __forceinline__ void mma_bf16(float* c, const uint32_t* a, uint32_t b0, uint32_t b1) {
    asm volatile(
        "mma.sync.aligned.m16n8k16.row.col.f32.bf16.bf16.f32 "
        "{%0,%1,%2,%3}, {%4,%5,%6,%7}, {%8,%9}, {%0,%1,%2,%3};"
        : "+f"(c[0]), "+f"(c[1]), "+f"(c[2]), "+f"(c[3])
        : "r"(a[0]), "r"(a[1]), "r"(a[2]), "r"(a[3]), "r"(b0), "r"(b1));
}
__device__ __forceinline__ float block_max256(float v, float* sh) {
    int lane = threadIdx.x & 31, w = threadIdx.x >> 5;
#pragma unroll
    for (int o = 16; o; o >>= 1) v = fmaxf(v, __shfl_xor_sync(0xffffffffu, v, o));
    if (lane == 0) sh[w] = v;
    __syncthreads();
    if (w == 0) {
        v = (lane < 8) ? sh[lane] : 0.0f;
#pragma unroll
        for (int o = 4; o; o >>= 1) v = fmaxf(v, __shfl_xor_sync(0xffffffffu, v, o));
        if (lane == 0) sh[0] = v;
    }
    __syncthreads();
    v = sh[0];
    __syncthreads();
    return v;
}
__device__ __forceinline__ unsigned short qb(float x, float s) {
    return __bfloat16_as_ushort(__float2bfloat16_rn(rintf(__fdiv_rn(x, s))));
}

// ---------------- preprocessing kernels ------------------------------------
__global__ void zero_mask_kernel() {
    for (int k = threadIdx.x; k < KDIM; k += blockDim.x) d_mask[k] = 0;
}

__global__ __launch_bounds__(256) void find_outliers_kernel(const float* __restrict__ X,
                                                            const float* __restrict__ sigma,
                                                            int total4) {
    int i = blockIdx.x * 256 + threadIdx.x;
    if (i >= total4) return;
    float s = sigma[0];
    float4 v = reinterpret_cast<const float4*>(X)[i];
    int k = (i * 4) & (KDIM - 1);
    if (fabsf(v.x) > s) d_mask[k + 0] = 1;
    if (fabsf(v.y) > s) d_mask[k + 1] = 1;
    if (fabsf(v.z) > s) d_mask[k + 2] = 1;
    if (fabsf(v.w) > s) d_mask[k + 3] = 1;
}

// deterministic, ordered compaction by a single warp
__global__ void compact_kernel() {
    int lane = threadIdx.x;
    int base = 0;
    for (int it = 0; it < KDIM / 32; it++) {
        int k = it * 32 + lane;
        int p = (d_mask[k] != 0);
        unsigned bal = __ballot_sync(0xffffffffu, p);
        if (p) d_oidx[base + __popc(bal & ((1u << lane) - 1u))] = k;
        base += __popc(bal);
    }
    if (lane == 0) d_ocnt = base;
}

__global__ __launch_bounds__(256) void quant_w_kernel(const float* __restrict__ W) {
    __shared__ float sh[32];
    int n = blockIdx.x, tid = threadIdx.x;
    const float4* row = reinterpret_cast<const float4*>(W + (size_t)n * KDIM);
    float4 v[4];
    float amax = 0.0f;
#pragma unroll
    for (int i = 0; i < 4; i++) {
        v[i] = row[i * 256 + tid];
        amax = fmaxf(amax, fmaxf(fmaxf(fabsf(v[i].x), fabsf(v[i].y)),
                                 fmaxf(fabsf(v[i].z), fabsf(v[i].w))));
    }
    amax = block_max256(amax, sh);
    float scale = amax * (1.0f / 64.0f);   // exact (power of 2)
    if (tid == 0) d_scale_col[n] = scale;
    ushort4* out = reinterpret_cast<ushort4*>(d_qw + (size_t)n * KDIM);
#pragma unroll
    for (int i = 0; i < 4; i++) {
        ushort4 u;
        u.x = qb(v[i].x, scale); u.y = qb(v[i].y, scale);
        u.z = qb(v[i].z, scale); u.w = qb(v[i].w, scale);
        out[i * 256 + tid] = u;
    }
}

__global__ __launch_bounds__(256) void quant_x_kernel(const float* __restrict__ X) {
    __shared__ float sh[32];
    int m = blockIdx.x, tid = threadIdx.x;
    const float4* row = reinterpret_cast<const float4*>(X + (size_t)m * KDIM);
    const int4* mk4 = reinterpret_cast<const int4*>(d_mask);
    float4 v[4];
    int4 mk[4];
    float amax = 0.0f;
#pragma unroll
    for (int i = 0; i < 4; i++) {
        v[i] = row[i * 256 + tid];
        mk[i] = mk4[i * 256 + tid];
        float ax = mk[i].x ? 0.0f : fabsf(v[i].x);
        float ay = mk[i].y ? 0.0f : fabsf(v[i].y);
        float az = mk[i].z ? 0.0f : fabsf(v[i].z);
        float aw = mk[i].w ? 0.0f : fabsf(v[i].w);
        amax = fmaxf(amax, fmaxf(fmaxf(ax, ay), fmaxf(az, aw)));
    }
    amax = block_max256(amax, sh);
    float xs = fmaxf(__fdiv_rn(amax, 127.0f), 1e-8f);
    if (tid == 0) d_x_scale[m] = xs;
    ushort4* out = reinterpret_cast<ushort4*>(d_qx + (size_t)m * KDIM);
#pragma unroll
    for (int i = 0; i < 4; i++) {
        ushort4 u;
        u.x = mk[i].x ? (unsigned short)0 : qb(v[i].x, xs);
        u.y = mk[i].y ? (unsigned short)0 : qb(v[i].y, xs);
        u.z = mk[i].z ? (unsigned short)0 : qb(v[i].z, xs);
        u.w = mk[i].w ? (unsigned short)0 : qb(v[i].w, xs);
        out[i * 256 + tid] = u;
    }
}

// ---------------- main GEMM: 128x128x32 tiles, bf16 mma.sync, cp.async -----
__global__ __launch_bounds__(256) void gemm_kernel(const float* __restrict__ X,
                                                   float* __restrict__ Y) {
    __shared__ __align__(16) __nv_bfloat16 sA[2][128][40];
    __shared__ __align__(16) __nv_bfloat16 sB[2][128][40];

    const int tid = threadIdx.x;
    const int lane = tid & 31, wid = tid >> 5;
    const int wm = wid >> 2, wn = wid & 3;             // 2 x 4 warp grid
    const int m0 = blockIdx.y * 128, n0 = blockIdx.x * 128;

    const __nv_bfloat16* gA = d_qx + (size_t)m0 * KDIM;
    const __nv_bfloat16* gB = d_qw + (size_t)n0 * KDIM;

    const int lrow = tid >> 2;             // 0..63
    const int lcol = (tid & 3) << 3;       // 0,8,16,24 (bf16 units)

    float acc[4][4][4];
#pragma unroll
    for (int a = 0; a < 4; a++)
#pragma unroll
        for (int b = 0; b < 4; b++)
#pragma unroll
            for (int c = 0; c < 4; c++) acc[a][b][c] = 0.0f;

    // ldmatrix address patterns
    const int aRow = lane & 15;
    const int aCol = (lane >> 4) << 3;
    const int bRow = ((lane >> 4) << 3) + (lane & 7);
    const int bCol = ((lane >> 3) & 1) << 3;

    auto load_tile = [&](int buf, int kk) {
#pragma unroll
        for (int r = 0; r < 2; r++) {
            int row = lrow + r * 64;
            cp_async16((uint32_t)__cvta_generic_to_shared(&sA[buf][row][lcol]),
                       gA + (size_t)row * KDIM + kk + lcol);
            cp_async16((uint32_t)__cvta_generic_to_shared(&sB[buf][row][lcol]),
                       gB + (size_t)row * KDIM + kk + lcol);
        }
        cp_commit();
    };

    load_tile(0, 0);

    const int kTiles = KDIM / 32;
    for (int t = 0; t < kTiles; t++) {
        if (t + 1 < kTiles) { load_tile((t + 1) & 1, (t + 1) * 32); cp_wait<1>(); }
        else               { cp_wait<0>(); }
        __syncthreads();
        const int buf = t & 1;
#pragma unroll
        for (int ks = 0; ks < 2; ks++) {
            uint32_t af[4][4], bfr[2][4];
#pragma unroll
            for (int mt = 0; mt < 4; mt++)
                ldm_x4(af[mt], &sA[buf][wm * 64 + mt * 16 + aRow][ks * 16 + aCol]);
#pragma unroll
            for (int np = 0; np < 2; np++)
                ldm_x4(bfr[np], &sB[buf][wn * 32 + np * 16 + bRow][ks * 16 + bCol]);
#pragma unroll
            for (int mt = 0; mt < 4; mt++)
#pragma unroll
                for (int nt = 0; nt < 4; nt++)
                    mma_bf16(acc[mt][nt], af[mt],
                             bfr[nt >> 1][(nt & 1) * 2], bfr[nt >> 1][(nt & 1) * 2 + 1]);
        }
        __syncthreads();
    }

    // ---------------- epilogue ---------------------------------------------
    const int g = lane >> 2, q = lane & 3;

    // per-row activation scale
    float xs0[4], xs1[4];
#pragma unroll
    for (int mt = 0; mt < 4; mt++) {
        int mr = m0 + wm * 64 + mt * 16 + g;
        xs0[mt] = d_x_scale[mr];
        xs1[mt] = d_x_scale[mr + 8];
    }
#pragma unroll
    for (int mt = 0; mt < 4; mt++)
#pragma unroll
        for (int nt = 0; nt < 4; nt++) {
            acc[mt][nt][0] *= xs0[mt]; acc[mt][nt][1] *= xs0[mt];
            acc[mt][nt][2] *= xs1[mt]; acc[mt][nt][3] *= xs1[mt];
        }

    // fp32 outlier rank-C correction, staged through (now free) smem
    float* xcol = reinterpret_cast<float*>(&sA[0][0][0]);
    float* wcol = xcol + 128;
    const int cnt = d_ocnt;
    for (int c = 0; c < cnt; c++) {
        int kj = d_oidx[c];
        __syncthreads();
        if (tid < 128)
            xcol[tid] = X[(size_t)(m0 + tid) * KDIM + kj];
        else if (tid < 256)
            wcol[tid - 128] = __bfloat162float(d_qw[(size_t)(n0 + tid - 128) * KDIM + kj]);
        __syncthreads();
        float xv0[4], xv1[4], wv0[4], wv1[4];
#pragma unroll
        for (int mt = 0; mt < 4; mt++) {
            xv0[mt] = xcol[wm * 64 + mt * 16 + g];
            xv1[mt] = xcol[wm * 64 + mt * 16 + 8 + g];
        }
#pragma unroll
        for (int nt = 0; nt < 4; nt++) {
            wv0[nt] = wcol[wn * 32 + nt * 8 + q * 2];
            wv1[nt] = wcol[wn * 32 + nt * 8 + q * 2 + 1];
        }
#pragma unroll
        for (int mt = 0; mt < 4; mt++)
#pragma unroll
            for (int nt = 0; nt < 4; nt++) {
                acc[mt][nt][0] += xv0[mt] * wv0[nt];
                acc[mt][nt][1] += xv0[mt] * wv1[nt];
                acc[mt][nt][2] += xv1[mt] * wv0[nt];
                acc[mt][nt][3] += xv1[mt] * wv1[nt];
            }
    }

    // per-col weight scale + store
#pragma unroll
    for (int mt = 0; mt < 4; mt++) {
        int m1 = m0 + wm * 64 + mt * 16 + g;
#pragma unroll
        for (int nt = 0; nt < 4; nt++) {
            int n = n0 + wn * 32 + nt * 8 + q * 2;
            float sc0 = d_scale_col[n], sc1 = d_scale_col[n + 1];
            float2 r0 = make_float2(acc[mt][nt][0] * sc0, acc[mt][nt][1] * sc1);
            float2 r1 = make_float2(acc[mt][nt][2] * sc0, acc[mt][nt][3] * sc1);
            *reinterpret_cast<float2*>(&Y[(size_t)m1 * NDIM + n]) = r0;
            *reinterpret_cast<float2*>(&Y[(size_t)(m1 + 8) * NDIM + n]) = r1;
        }
    }
}

// ---------------- launcher --------------------------------------------------
extern "C" void kernel_launch(void* const* d_in, const int* in_sizes, int n_in,
                              void* d_out, int out_size) {
    const float* x   = (const float*)d_in[0];
    const float* w   = (const float*)d_in[1];
    const float* sig = (const float*)d_in[2];
    float* y = (float*)d_out;

    const int M = in_sizes[0] / KDIM;   // 8192
    (void)n_in; (void)out_size;

    zero_mask_kernel<<<1, 256>>>();
    {
        int total4 = M * KDIM / 4;
        find_outliers_kernel<<<(total4 + 255) / 256, 256>>>(x, sig, total4);
    }
    compact_kernel<<<1, 32>>>();
    quant_w_kernel<<<NDIM, 256>>>(w);
    quant_x_kernel<<<M, 256>>>(x);

    dim3 grid(NDIM / 128, M / 128);
    gemm_kernel<<<grid, 256>>>(x, y);
}